// round 6
// baseline (speedup 1.0000x reference)
#include <cuda_runtime.h>

// MySoftBCELoss: B=524288, C=64, f32 -> scalar f32.
// l = argmax(target_row); per_sample = t[l]*log(clip(sig(x[l]))) + log(clip(sig(-x[0])))
// out = -mean(per_sample)
// R6: persistent 592 CTAs, 16 rows/warp/iter, float4 loads + split-warp REDUX
// (one REDUX resolves two rows; results land directly in their finalize lanes).

static constexpr int B_ROWS        = 524288;
static constexpr int C_COLS        = 64;
static constexpr int ROWS_PER_TILE = 16;
static constexpr int PAIRS         = ROWS_PER_TILE / 2;           // 8
static constexpr int NTILES        = B_ROWS / ROWS_PER_TILE;      // 32768
static constexpr int THREADS       = 256;
static constexpr int WARPS_PER_BLOCK = THREADS / 32;              // 8
static constexpr int GRID          = 592;                         // 4 CTAs x 148 SMs
static constexpr int TOTAL_WARPS   = GRID * WARPS_PER_BLOCK;      // 4736

__device__ double   g_accum;    // zero at module load; reset by last block each replay
__device__ unsigned g_count;

__global__ __launch_bounds__(THREADS, 4)
void softbce_persistent_kernel(const float* __restrict__ logits,
                               const float* __restrict__ target,
                               float* __restrict__ out) {
    const int lane = threadIdx.x & 31;
    const int wid  = threadIdx.x >> 5;
    const int gw   = blockIdx.x * WARPS_PER_BLOCK + wid;

    const int      sub   = lane & 15;                 // position within half-warp
    const int      hi    = lane >> 4;                 // 0 = low half, 1 = high half
    const unsigned hmask = hi ? 0xFFFF0000u : 0x0000FFFFu;

    float partial = 0.0f;

    for (int tile = gw; tile < NTILES; tile += TOTAL_WARPS) {
        const long long row0 = (long long)tile * ROWS_PER_TILE;
        // Load k covers row pair (2k, 2k+1): low half-warp -> row 2k, high -> 2k+1.
        const float* tp = target + (row0 + hi) * C_COLS + sub * 4;

        // ---- 8 x LDG.128 per lane, front-batched (4KB/warp in flight),
        //      streaming (zero reuse) ----
        float4 v[PAIRS];
#pragma unroll
        for (int k = 0; k < PAIRS; k++)
            v[k] = __ldcs(reinterpret_cast<const float4*>(tp + k * 2 * C_COLS));

        // ---- x0 prefetch (independent of argmax) ----
        float x0 = 0.0f;
        if (sub < PAIRS)
            x0 = __ldg(logits + (row0 + 2 * sub + hi) * C_COLS);

        // ---- Argmax: ONE split-warp REDUX resolves TWO rows ----
        // target in [0,1) -> positive float bit order == value order.
        // key = (bits & ~0x3F) | (63 - col): ties -> smallest col (jnp.argmax
        // first-occurrence), value truncation error <= 2^-18 relative.
        unsigned my_key = 0;
#pragma unroll
        for (int k = 0; k < PAIRS; k++) {
            const int c0 = sub * 4;
            unsigned k0 = (__float_as_uint(v[k].x) & 0xFFFFFFC0u) | (unsigned)(63 - c0);
            unsigned k1 = (__float_as_uint(v[k].y) & 0xFFFFFFC0u) | (unsigned)(62 - c0);
            unsigned k2 = (__float_as_uint(v[k].z) & 0xFFFFFFC0u) | (unsigned)(61 - c0);
            unsigned k3 = (__float_as_uint(v[k].w) & 0xFFFFFFC0u) | (unsigned)(60 - c0);
            unsigned a = k0 > k1 ? k0 : k1;
            unsigned b = k2 > k3 ? k2 : k3;
            unsigned loc = a > b ? a : b;
            unsigned mx = __reduce_max_sync(hmask, loc);   // per-half reduction
            if (sub == k) my_key = mx;                     // lane k: row 2k; lane 16+k: row 2k+1
        }

        // ---- Finalize lanes 0..7 and 16..23: one row each ----
        if (sub < PAIRS) {
            int   idx  = 63 - (int)(my_key & 63u);
            float tval = __uint_as_float(my_key & 0xFFFFFFC0u);
            const long long r = row0 + 2 * sub + hi;
            float xl = __ldg(logits + r * C_COLS + idx);
            float pl = 1.0f / (1.0f + __expf(-xl));            // sigmoid(xl)
            pl = fminf(fmaxf(pl, 1e-7f), 1.0f - 1e-7f);
            float q0 = 1.0f / (1.0f + __expf(x0));             // 1 - sigmoid(x0)
            q0 = fminf(fmaxf(q0, 1e-7f), 1.0f - 1e-7f);
            partial += tval * __logf(pl) + __logf(q0);
        }
    }

    // ---- One block reduction total ----
    partial += __shfl_down_sync(0xffffffffu, partial, 16);
    partial += __shfl_down_sync(0xffffffffu, partial, 8);
    partial += __shfl_down_sync(0xffffffffu, partial, 4);
    partial += __shfl_down_sync(0xffffffffu, partial, 2);
    partial += __shfl_down_sync(0xffffffffu, partial, 1);

    __shared__ float s_warp[WARPS_PER_BLOCK];
    if (lane == 0) s_warp[wid] = partial;
    __syncthreads();

    if (wid == 0) {
        float s = (lane < WARPS_PER_BLOCK) ? s_warp[lane] : 0.0f;
        s += __shfl_down_sync(0xffffffffu, s, 4);
        s += __shfl_down_sync(0xffffffffu, s, 2);
        s += __shfl_down_sync(0xffffffffu, s, 1);
        if (lane == 0) {
            atomicAdd(&g_accum, (double)s);
            __threadfence();
            unsigned ticket = atomicAdd(&g_count, 1u);
            if (ticket == (unsigned)(GRID - 1)) {
                __threadfence();
                double total = atomicAdd(&g_accum, 0.0);   // coherent read
                out[0] = (float)(-total / (double)B_ROWS);
                g_accum = 0.0;                              // reset for next replay
                g_count = 0u;
            }
        }
    }
}

extern "C" void kernel_launch(void* const* d_in, const int* in_sizes, int n_in,
                              void* d_out, int out_size) {
    const float* logits = (const float*)d_in[0];
    const float* target = (const float*)d_in[1];
    float* out = (float*)d_out;
    softbce_persistent_kernel<<<GRID, THREADS>>>(logits, target, out);
}